// round 7
// baseline (speedup 1.0000x reference)
#include <cuda_runtime.h>
#include <math.h>

#define B      16384
#define DIN    12
#define HID    192
#define LAYERS 24
#define NB     66
#define CAP2   120
#define W2STR  194

// ---------------- scratch ----------------
__device__ float g_zk[(LAYERS + 1) * B * DIN];
__device__ float g_V [B * 72];
__device__ float g_ld[B];
__device__ float g_part[256];
__device__ float g_ssq;

// ---------------- f32x2 packed FMA ----------------
union F2U { float2 f; unsigned long long u; };
__device__ __forceinline__ float2 ffma2(float2 a, float2 b, float2 c) {
    F2U A, Bv, C, D; A.f = a; Bv.f = b; C.f = c;
    asm("fma.rn.f32x2 %0,%1,%2,%3;" : "=l"(D.u) : "l"(A.u), "l"(Bv.u), "l"(C.u));
    return D.f;
}

__device__ __forceinline__ float pick6(const float a[6], int i) {
    float r = a[0];
    if (i == 1) r = a[1];
    if (i == 2) r = a[2];
    if (i == 3) r = a[3];
    if (i == 4) r = a[4];
    if (i == 5) r = a[5];
    return r;
}

// ---------------- init ----------------
__global__ void k_init(const float* __restrict__ y, const float* __restrict__ Jp) {
    int i0 = blockIdx.x * blockDim.x + threadIdx.x;
    int st = gridDim.x * blockDim.x;
    for (int i = i0; i < B * 72; i += st) {
        g_V[i] = Jp[i];
        if (i < B * DIN) g_zk[LAYERS * B * DIN + i] = y[i];
        if (i < B)       g_ld[i] = 0.f;
    }
}

// smem float offsets
#define OFF_W2T  0
#define OFF_W3   37248
#define OFF_W1   39552
#define OFF_B1   40704
#define OFF_B2   40896
#define OFF_B3   41088
#define OFF_WARP 41104
#define WSTRIDE  1032
// per-warp block (floats): [0,960) entry area (inv h1 list as float2; vjp g-packets
// as float4 pairs, 32B/entry, CAP2=120), [960,1032) Vw

// ---------------- fused inverse + VJP layer ----------------
__global__ void __launch_bounds__(512) k_fused(
    const float* __restrict__ W1, const float* __restrict__ b1,
    const float* __restrict__ W2, const float* __restrict__ b2,
    const float* __restrict__ W3, const float* __restrict__ b3, int k)
{
    extern __shared__ float sm[];
    float* W2T = sm + OFF_W2T;   // [192][194]: W2T[j*194+c] = W2[c][j]
    float* W3s = sm + OFF_W3;    // [12][192]
    float* W1s = sm + OFF_W1;    // [192][6]
    float* b1s = sm + OFF_B1;
    float* b2s = sm + OFF_B2;
    float* b3s = sm + OFF_B3;

    int tid = threadIdx.x;
    for (int i = tid; i < HID * HID; i += 512) {
        int cout = i / HID, jin = i % HID;
        W2T[jin * W2STR + cout] = W2[i];
    }
    for (int i = tid; i < 12 * HID; i += 512) W3s[i] = W3[i];
    for (int i = tid; i < HID * 6; i += 512)  W1s[i] = W1[i];
    for (int i = tid; i < HID; i += 512) { b1s[i] = b1[i]; b2s[i] = b2[i]; }
    if (tid < 12) b3s[tid] = b3[tid];
    __syncthreads();

    int lane = tid & 31, wip = tid >> 5;
    float*  wb  = sm + OFF_WARP + wip * WSTRIDE;
    float2* pw  = (float2*)wb;       // inv h1 list
    float4* pw4 = (float4*)wb;       // vjp g-packets (2 float4 per entry)
    float*  Vw  = wb + 960;
    unsigned lt = (1u << lane) - 1u;

    int w  = (blockIdx.x * 512 + tid) >> 5;
    int nw = gridDim.x * 16;

    for (int b = w; b < B; b += nw) {
        // =========================== INVERSE PHASE ===========================
        __syncwarp();
        const float* zin = g_zk + ((size_t)(k + 1) * B + b) * DIN;
        float z1[6], z2[6];
#pragma unroll
        for (int j = 0; j < 6; j++) { z1[j] = zin[6 + j]; z2[j] = zin[j]; }
        float2 z1p[3];
#pragma unroll
        for (int q = 0; q < 3; q++) z1p[q] = make_float2(z1[2 * q], z1[2 * q + 1]);

        // L1: rows r = lane + 32i; pack (r*194 | r<<16) in entry word
        int base = 0;
#pragma unroll
        for (int i = 0; i < 6; i++) {
            int r = lane + 32 * i;
            const float2* w1r = (const float2*)(W1s + r * 6);
            float2 t0 = ffma2(w1r[0], z1p[0], make_float2(b1s[r], 0.f));
            t0 = ffma2(w1r[1], z1p[1], t0);
            t0 = ffma2(w1r[2], z1p[2], t0);
            float a = t0.x + t0.y;
            unsigned m = __ballot_sync(0xffffffffu, a > 0.f);
            if ((m >> lane) & 1u) {
                int pos = base + __popc(m & lt);
                pw[pos] = make_float2(a, __int_as_float((r * W2STR) | (r << 16)));
            }
            base += __popc(m);
        }
        int cnt1 = base;
        __syncwarp();

        // L2: 4-row unroll, list via LDS.128 pairs
        float2 h2p[3], h2q[3];
#pragma unroll
        for (int q = 0; q < 3; q++) {
            h2p[q] = ((const float2*)b2s)[q * 32 + lane];
            h2q[q] = make_float2(0.f, 0.f);
        }
        {
            int c = 0;
            for (; c + 4 <= cnt1; c += 4) {
                float4 L0 = pw4[c >> 1], L1 = pw4[(c >> 1) + 1];
                int r0 = __float_as_int(L0.y) & 0xFFFF;
                int r1 = __float_as_int(L0.w) & 0xFFFF;
                int r2 = __float_as_int(L1.y) & 0xFFFF;
                int r3 = __float_as_int(L1.w) & 0xFFFF;
                float2 h0 = make_float2(L0.x, L0.x), h1v = make_float2(L0.z, L0.z);
                float2 h2v = make_float2(L1.x, L1.x), h3v = make_float2(L1.z, L1.z);
#pragma unroll
                for (int q = 0; q < 3; q++) {
                    int co = 64 * q + 2 * lane;
                    h2p[q] = ffma2(*(const float2*)(W2T + r0 + co), h0, h2p[q]);
                    h2q[q] = ffma2(*(const float2*)(W2T + r1 + co), h1v, h2q[q]);
                    h2p[q] = ffma2(*(const float2*)(W2T + r2 + co), h2v, h2p[q]);
                    h2q[q] = ffma2(*(const float2*)(W2T + r3 + co), h3v, h2q[q]);
                }
            }
            for (; c < cnt1; c++) {
                float2 p0 = pw[c];
                int r0 = __float_as_int(p0.y) & 0xFFFF;
                float2 h0 = make_float2(p0.x, p0.x);
#pragma unroll
                for (int q = 0; q < 3; q++)
                    h2p[q] = ffma2(*(const float2*)(W2T + r0 + 64 * q + 2 * lane), h0, h2p[q]);
            }
        }
        unsigned mm2[6];
        float2 h2r[3];
#pragma unroll
        for (int q = 0; q < 3; q++) {
            float hx = h2p[q].x + h2q[q].x;
            float hy = h2p[q].y + h2q[q].y;
            mm2[2 * q]     = __ballot_sync(0xffffffffu, hx > 0.f);
            mm2[2 * q + 1] = __ballot_sync(0xffffffffu, hy > 0.f);
            h2r[q] = make_float2(fmaxf(hx, 0.f), fmaxf(hy, 0.f));
        }

        // L3
        float pp[12];
#pragma unroll
        for (int o = 0; o < 12; o++) {
            float2 acc = make_float2(0.f, 0.f);
#pragma unroll
            for (int q = 0; q < 3; q++)
                acc = ffma2(((const float2*)(W3s + o * HID))[q * 32 + lane], h2r[q], acc);
            float a = acc.x + acc.y;
#pragma unroll
            for (int off = 16; off > 0; off >>= 1) a += __shfl_xor_sync(0xffffffffu, a, off);
            pp[o] = a;
        }

        // epilogue
        float ssum = 0.f, znew[6], es[6], fac[6];
#pragma unroll
        for (int j = 0; j < 6; j++) {
            float sh = pp[2 * j] + b3s[2 * j];
            float sr = pp[2 * j + 1] + b3s[2 * j + 1];
            float s  = 2.f * tanhf(0.5f * sr);
            ssum += s;
            float em = expf(-s);
            znew[j] = (z2[j] - sh) * em;
            es[j]   = expf(s);
            float t2 = 0.5f * s;
            fac[j]  = znew[j] * es[j] * (1.f - t2 * t2);
        }
        {
            float* zo = g_zk + ((size_t)k * B + b) * DIN;
            if (lane < 12) zo[lane] = (lane < 6) ? pick6(z1, lane) : pick6(znew, lane - 6);
            if (lane == 31) g_ld[b] -= ssum;
        }

        // ============================= VJP PHASE =============================
        for (int t = lane; t < 72; t += 32) Vw[t] = g_V[(size_t)b * 72 + t];

        // read m1-compact packed words BEFORE gpair clobbers pw
        int cmax = cnt1 < 128 ? cnt1 : 128;
        int ccb[4];
#pragma unroll
        for (int t = 0; t < 4; t++) {
            int p = lane + 32 * t;
            ccb[t] = (p < cmax) ? __float_as_int(pw[p].y) : 0;
        }
        int ccf[4];
#pragma unroll
        for (int t = 0; t < 4; t++) ccf[t] = ccb[t] & 0xFFFF;
        // tail pre-reads (rare)
        bool hastail = (cnt1 > 128);
        int tb[2]; bool t2v[2];
        if (hastail) {
#pragma unroll
            for (int t2 = 0; t2 < 2; t2++) {
                int p = 128 + lane + 32 * t2;
                t2v[t2] = (p < cnt1);
                tb[t2] = t2v[t2] ? __float_as_int(pw[p].y) : 0;
            }
        }
        __syncwarp();

        // step 1: accp[v][q] (halves = cols 64q+2*lane, +1)
        float2 accp[6][3];
#pragma unroll
        for (int v = 0; v < 6; v++)
#pragma unroll
            for (int q = 0; q < 3; q++) accp[v][q] = make_float2(0.f, 0.f);
#pragma unroll
        for (int j = 0; j < 6; j++) {
            float2 gv2[6], gf2[6];
#pragma unroll
            for (int v = 0; v < 6; v++) {
                float g = Vw[v * 12 + j];
                gv2[v] = make_float2(g, g);
                float gf = g * fac[j];
                gf2[v] = make_float2(gf, gf);
            }
#pragma unroll
            for (int q = 0; q < 3; q++) {
                float2 wsh = ((const float2*)(W3s + (2 * j) * HID))[q * 32 + lane];
                float2 wsr = ((const float2*)(W3s + (2 * j + 1) * HID))[q * 32 + lane];
#pragma unroll
                for (int v = 0; v < 6; v++) {
                    accp[v][q] = ffma2(wsh, gv2[v], accp[v][q]);
                    accp[v][q] = ffma2(wsr, gf2[v], accp[v][q]);
                }
            }
        }

        // compact m2-active rows into 32B packets (capacity CAP2, exact overflow)
        int pre = 0;
#pragma unroll
        for (int g2 = 0; g2 < 6; g2++) pre += __popc(mm2[g2]);
        bool hasov = (pre > CAP2);
        unsigned ovm[6];
        int base2 = 0;
#pragma unroll
        for (int g2 = 0; g2 < 6; g2++) {
            int q = g2 >> 1, h = g2 & 1;
            unsigned m = mm2[g2], keep = m;
            if (hasov) {
                int pc = __popc(m);
                int ovc = base2 + pc - CAP2;
                if (ovc > 0) {
                    if (ovc > pc) ovc = pc;
                    for (int t = 0; t < ovc; t++) keep &= ~(0x80000000u >> __clz(keep));
                }
            }
            ovm[g2] = m ^ keep;
            if ((keep >> lane) & 1u) {
                int pos = base2 + __popc(keep & lt);
                float g0 = h ? accp[0][q].y : accp[0][q].x;
                float g1 = h ? accp[1][q].y : accp[1][q].x;
                float g2v = h ? accp[2][q].y : accp[2][q].x;
                float g3 = h ? accp[3][q].y : accp[3][q].x;
                float g4 = h ? accp[4][q].y : accp[4][q].x;
                float g5 = h ? accp[5][q].y : accp[5][q].x;
                pw4[pos * 2 + 0] = make_float4(g0, g1, g2v, g3);
                pw4[pos * 2 + 1] = make_float4(g4, g5, __int_as_float(64 * q + 2 * lane + h), 0.f);
            }
            base2 += __popc(keep);
        }
        int cnt2 = base2;
        __syncwarp();

        // main loop: 128 compacted output columns, 2 LDS.128 + 4 gathers per row
        float2 a1p[4][3];
#pragma unroll
        for (int t = 0; t < 4; t++)
#pragma unroll
            for (int p = 0; p < 3; p++) a1p[t][p] = make_float2(0.f, 0.f);
#pragma unroll 2
        for (int c = 0; c < cnt2; c++) {
            float4 e0 = pw4[c * 2], e1 = pw4[c * 2 + 1];
            int jj = __float_as_int(e1.z);
            float wv0 = W2T[ccf[0] + jj];
            float wv1 = W2T[ccf[1] + jj];
            float wv2 = W2T[ccf[2] + jj];
            float wv3 = W2T[ccf[3] + jj];
            float2 g01 = make_float2(e0.x, e0.y);
            float2 g23 = make_float2(e0.z, e0.w);
            float2 g45 = make_float2(e1.x, e1.y);
            float2 w0 = make_float2(wv0, wv0), w1v = make_float2(wv1, wv1);
            float2 w2v = make_float2(wv2, wv2), w3v = make_float2(wv3, wv3);
            a1p[0][0] = ffma2(g01, w0, a1p[0][0]);
            a1p[0][1] = ffma2(g23, w0, a1p[0][1]);
            a1p[0][2] = ffma2(g45, w0, a1p[0][2]);
            a1p[1][0] = ffma2(g01, w1v, a1p[1][0]);
            a1p[1][1] = ffma2(g23, w1v, a1p[1][1]);
            a1p[1][2] = ffma2(g45, w1v, a1p[1][2]);
            a1p[2][0] = ffma2(g01, w2v, a1p[2][0]);
            a1p[2][1] = ffma2(g23, w2v, a1p[2][1]);
            a1p[2][2] = ffma2(g45, w2v, a1p[2][2]);
            a1p[3][0] = ffma2(g01, w3v, a1p[3][0]);
            a1p[3][1] = ffma2(g23, w3v, a1p[3][1]);
            a1p[3][2] = ffma2(g45, w3v, a1p[3][2]);
        }

        // tail: columns 128..cnt1 (ultra-rare)
        float a1s0[6], a1s1[6];
        if (hastail) {
#pragma unroll
            for (int v = 0; v < 6; v++) { a1s0[v] = 0.f; a1s1[v] = 0.f; }
            int co0 = tb[0] & 0xFFFF, co1 = tb[1] & 0xFFFF;
            for (int c = 0; c < cnt2; c++) {
                float4 e0 = pw4[c * 2], e1 = pw4[c * 2 + 1];
                int jj = __float_as_int(e1.z);
                float wa = W2T[co0 + jj], wbv = W2T[co1 + jj];
                a1s0[0] = fmaf(e0.x, wa, a1s0[0]); a1s0[1] = fmaf(e0.y, wa, a1s0[1]);
                a1s0[2] = fmaf(e0.z, wa, a1s0[2]); a1s0[3] = fmaf(e0.w, wa, a1s0[3]);
                a1s0[4] = fmaf(e1.x, wa, a1s0[4]); a1s0[5] = fmaf(e1.y, wa, a1s0[5]);
                a1s1[0] = fmaf(e0.x, wbv, a1s1[0]); a1s1[1] = fmaf(e0.y, wbv, a1s1[1]);
                a1s1[2] = fmaf(e0.z, wbv, a1s1[2]); a1s1[3] = fmaf(e0.w, wbv, a1s1[3]);
                a1s1[4] = fmaf(e1.x, wbv, a1s1[4]); a1s1[5] = fmaf(e1.y, wbv, a1s1[5]);
            }
        }

        // overflow fallback (exact; ultra-rare)
        if (hasov) {
#pragma unroll
            for (int g2 = 0; g2 < 6; g2++) {
                int q = g2 >> 1, h = g2 & 1;
                unsigned ov = ovm[g2];
                while (ov) {
                    int src = __ffs(ov) - 1; ov &= ov - 1;
                    float gg[6];
#pragma unroll
                    for (int v = 0; v < 6; v++) {
                        F2U u; u.f = accp[v][q];
                        u.u = __shfl_sync(0xffffffffu, u.u, src);
                        gg[v] = h ? u.f.y : u.f.x;
                    }
                    int cout = 64 * q + 2 * src + h;
#pragma unroll
                    for (int t = 0; t < 4; t++) {
                        float wv = W2T[ccf[t] + cout];
                        a1p[t][0].x = fmaf(gg[0], wv, a1p[t][0].x);
                        a1p[t][0].y = fmaf(gg[1], wv, a1p[t][0].y);
                        a1p[t][1].x = fmaf(gg[2], wv, a1p[t][1].x);
                        a1p[t][1].y = fmaf(gg[3], wv, a1p[t][1].y);
                        a1p[t][2].x = fmaf(gg[4], wv, a1p[t][2].x);
                        a1p[t][2].y = fmaf(gg[5], wv, a1p[t][2].y);
                    }
                    if (hastail) {
                        float wa = W2T[(tb[0] & 0xFFFF) + cout], wbv = W2T[(tb[1] & 0xFFFF) + cout];
#pragma unroll
                        for (int v = 0; v < 6; v++) {
                            a1s0[v] = fmaf(gg[v], wa, a1s0[v]);
                            a1s1[v] = fmaf(gg[v], wbv, a1s1[v]);
                        }
                    }
                }
            }
        }

        // fold a1 -> pz via W1 rows (indices from packed high byte)
        float2 pzp[6][3];
#pragma unroll
        for (int v = 0; v < 6; v++)
#pragma unroll
            for (int jp = 0; jp < 3; jp++) pzp[v][jp] = make_float2(0.f, 0.f);
#pragma unroll
        for (int t = 0; t < 4; t++) {
            int p = lane + 32 * t;
            if (p < cmax) {
                int cc = ccb[t] >> 16;
                const float2* w1r = (const float2*)(W1s + cc * 6);
                float2 wA = w1r[0], wB = w1r[1], wC = w1r[2];
#pragma unroll
                for (int vp = 0; vp < 3; vp++) {
                    float a0 = a1p[t][vp].x, a1 = a1p[t][vp].y;
                    float2 a02 = make_float2(a0, a0), a12 = make_float2(a1, a1);
                    pzp[2 * vp][0]     = ffma2(wA, a02, pzp[2 * vp][0]);
                    pzp[2 * vp][1]     = ffma2(wB, a02, pzp[2 * vp][1]);
                    pzp[2 * vp][2]     = ffma2(wC, a02, pzp[2 * vp][2]);
                    pzp[2 * vp + 1][0] = ffma2(wA, a12, pzp[2 * vp + 1][0]);
                    pzp[2 * vp + 1][1] = ffma2(wB, a12, pzp[2 * vp + 1][1]);
                    pzp[2 * vp + 1][2] = ffma2(wC, a12, pzp[2 * vp + 1][2]);
                }
            }
        }
        if (hastail) {
#pragma unroll
            for (int t2 = 0; t2 < 2; t2++) {
                if (t2v[t2]) {
                    int cc = tb[t2] >> 16;
                    const float* w1r = W1s + cc * 6;
                    const float* as = t2 ? a1s1 : a1s0;
#pragma unroll
                    for (int v = 0; v < 6; v++)
#pragma unroll
                        for (int jp = 0; jp < 3; jp++) {
                            pzp[v][jp].x = fmaf(as[v], w1r[2 * jp],     pzp[v][jp].x);
                            pzp[v][jp].y = fmaf(as[v], w1r[2 * jp + 1], pzp[v][jp].y);
                        }
                }
            }
        }

        // butterfly reduce (64-bit shuffles)
#pragma unroll
        for (int v = 0; v < 6; v++)
#pragma unroll
            for (int jp = 0; jp < 3; jp++) {
                F2U u; u.f = pzp[v][jp];
#pragma unroll
                for (int off = 16; off > 0; off >>= 1) {
                    F2U o2; o2.u = __shfl_xor_sync(0xffffffffu, u.u, off);
                    u.f.x += o2.f.x; u.f.y += o2.f.y;
                }
                pzp[v][jp] = u.f;
            }

        if (lane == 0) {
            float* vo = g_V + (size_t)b * 72;
#pragma unroll
            for (int v = 0; v < 6; v++)
#pragma unroll
                for (int j = 0; j < 6; j++) {
                    float pz = (j & 1) ? pzp[v][j >> 1].y : pzp[v][j >> 1].x;
                    vo[v * 12 + j]     = Vw[v * 12 + 6 + j] + pz;
                    vo[v * 12 + 6 + j] = Vw[v * 12 + j] * es[j];
                }
        }
    }
}

// ---------------- deterministic Frobenius-norm reduction ----------------
__global__ void k_ssq_part() {
    float s = 0.f;
    for (int i = blockIdx.x * blockDim.x + threadIdx.x; i < B * 72; i += gridDim.x * blockDim.x) {
        float v = g_V[i]; s += v * v;
    }
    __shared__ float red[256];
    red[threadIdx.x] = s; __syncthreads();
    for (int o = 128; o > 0; o >>= 1) {
        if (threadIdx.x < o) red[threadIdx.x] += red[threadIdx.x + o];
        __syncthreads();
    }
    if (threadIdx.x == 0) g_part[blockIdx.x] = red[0];
}
__global__ void k_ssq_final() {
    __shared__ float red[256];
    red[threadIdx.x] = g_part[threadIdx.x]; __syncthreads();
    for (int o = 128; o > 0; o >>= 1) {
        if (threadIdx.x < o) red[threadIdx.x] += red[threadIdx.x + o];
        __syncthreads();
    }
    if (threadIdx.x == 0) g_ssq = red[0];
}

// ---------------- KL + log_prob ----------------
#define LIX(r, c) ((r) * ((r) + 1) / 2 + (c))

__global__ void __launch_bounds__(64) k_kl(
    const float* __restrict__ Wsym, const float* __restrict__ lvd,
    float* __restrict__ out)
{
    __shared__ float As[NB * 144];
    for (int i = threadIdx.x; i < NB * 144; i += 64) {
        int m = i / 144; int rc = i % 144; int r = rc / 12; int c = rc % 12;
        As[i] = Wsym[m * 144 + r * 12 + c] - Wsym[m * 144 + c * 12 + r];
    }
    __syncthreads();

    int b = blockIdx.x * 64 + threadIdx.x;
    if (b >= B) return;

    float zr[12]; float zz = 0.f;
#pragma unroll
    for (int i = 0; i < 12; i++) { zr[i] = g_zk[(size_t)b * 12 + i]; zz += zr[i] * zr[i]; }
    out[b] = g_ld[b] - 6.f * 1.8378770664093453f - 0.5f * zz;

    float scale = rsqrtf(g_ssq);
    float Jp[6][12];
#pragma unroll
    for (int v = 0; v < 6; v++)
#pragma unroll
        for (int i = 0; i < 12; i++) Jp[v][i] = g_V[(size_t)b * 72 + v * 12 + i] * scale;

    float Sql[78];
#pragma unroll
    for (int i = 0; i < 78; i++) Sql[i] = 0.f;
    float trq = 0.f, trpq = 0.f;

    for (int m = 0; m < NB; m++) {
        const float* Am = As + m * 144;
        float Jq[12];
#pragma unroll
        for (int jj = 0; jj < 12; jj++) {
            float a = 0.f;
#pragma unroll
            for (int i = 0; i < 12; i++) a = fmaf(zr[i], Am[jj * 12 + i], a);
            Jq[jj] = a; trq = fmaf(a, a, trq);
        }
#pragma unroll
        for (int n = 0; n < 12; n++)
#pragma unroll
            for (int mm = 0; mm <= n; mm++) Sql[LIX(n, mm)] = fmaf(Jq[n], Jq[mm], Sql[LIX(n, mm)]);
#pragma unroll
        for (int v = 0; v < 6; v++) {
            float d = 0.f;
#pragma unroll
            for (int i = 0; i < 12; i++) d = fmaf(Jp[v][i], Jq[i], d);
            trpq = fmaf(d, d, trpq);
        }
    }

    float Ml[21];
#pragma unroll
    for (int a = 0; a < 6; a++)
#pragma unroll
        for (int c = 0; c <= a; c++) {
            float acc = 0.f;
#pragma unroll
            for (int i = 0; i < 12; i++) acc = fmaf(Jp[a][i], Jp[c][i], acc);
            Ml[LIX(a, c)] = acc;
        }
#pragma unroll
    for (int d = 0; d < 6; d++) Ml[LIX(d, d)] += 1e-3f;
    float dm = 0.f;
#pragma unroll
    for (int d = 0; d < 6; d++) dm += Ml[LIX(d, d)];
    float normM = fmaxf(dm * (1.f / 6.f), 1e-6f);
#pragma unroll
    for (int d = 0; d < 6; d++) Ml[LIX(d, d)] += 1e-3f * normM;

    float D[12];
#pragma unroll
    for (int i = 0; i < 12; i++) D[i] = expf(-lvd[i]);
#pragma unroll
    for (int d = 0; d < 12; d++) Sql[LIX(d, d)] += D[d];
    float dh = 0.f;
#pragma unroll
    for (int d = 0; d < 12; d++) dh += Sql[LIX(d, d)];
    float normH = fmaxf(dh * (1.f / 12.f), 1e-6f);
#pragma unroll
    for (int d = 0; d < 12; d++) Sql[LIX(d, d)] += 1e-3f * normH;

    float Db[12], sumDb = 0.f;
#pragma unroll
    for (int i = 0; i < 12; i++) { Db[i] = D[i] + 1e-3f * normH; sumDb += Db[i]; }

    float trp = 0.f;
#pragma unroll
    for (int v = 0; v < 6; v++)
#pragma unroll
        for (int i = 0; i < 12; i++) trp = fmaf(Jp[v][i] * Jp[v][i], Db[i], trp);

    float trace = (1e-3f + 1e-3f * normM) * (sumDb + trq) + trp + trpq;

    float ldM = 0.f;
#pragma unroll
    for (int c = 0; c < 6; c++) {
        float d = Ml[LIX(c, c)];
#pragma unroll
        for (int kk = 0; kk < c; kk++) d -= Ml[LIX(c, kk)] * Ml[LIX(c, kk)];
        d = sqrtf(d); ldM += 2.f * logf(d);
        float inv = 1.f / d;
#pragma unroll
        for (int r = c + 1; r < 6; r++) {
            float a = Ml[LIX(r, c)];
#pragma unroll
            for (int kk = 0; kk < c; kk++) a -= Ml[LIX(r, kk)] * Ml[LIX(c, kk)];
            Ml[LIX(r, c)] = a * inv;
        }
    }
    float ldH = 0.f;
#pragma unroll
    for (int c = 0; c < 12; c++) {
        float d = Sql[LIX(c, c)];
#pragma unroll
        for (int kk = 0; kk < c; kk++) d -= Sql[LIX(c, kk)] * Sql[LIX(c, kk)];
        d = sqrtf(d); ldH += 2.f * logf(d);
        float inv = 1.f / d;
#pragma unroll
        for (int r = c + 1; r < 12; r++) {
            float a = Sql[LIX(r, c)];
#pragma unroll
            for (int kk = 0; kk < c; kk++) a -= Sql[LIX(r, kk)] * Sql[LIX(c, kk)];
            Sql[LIX(r, c)] = a * inv;
        }
    }

    float logdet_p = ldM + 6.f * (-6.907755278982137f);
    out[B + b] = 0.5f * (trace - logdet_p - ldH - 12.f);
}

// ---------------- host launcher ----------------
extern "C" void kernel_launch(void* const* d_in, const int* in_sizes, int n_in,
                              void* d_out, int out_size) {
    const float* y    = (const float*)d_in[0];
    const float* Jp   = (const float*)d_in[1];
    const float* W1   = (const float*)d_in[2];
    const float* b1   = (const float*)d_in[3];
    const float* W2   = (const float*)d_in[4];
    const float* b2   = (const float*)d_in[5];
    const float* W3   = (const float*)d_in[6];
    const float* b3   = (const float*)d_in[7];
    const float* Wsym = (const float*)d_in[8];
    const float* lvd  = (const float*)d_in[9];
    float* out = (float*)d_out;

    const int SMEM_F = (OFF_WARP + 16 * WSTRIDE) * 4;  // 230,464 B
    cudaFuncSetAttribute(k_fused, cudaFuncAttributeMaxDynamicSharedMemorySize, SMEM_F);

    k_init<<<256, 256>>>(y, Jp);

    for (int k = LAYERS - 1; k >= 0; k--) {
        k_fused<<<152, 512, SMEM_F>>>(
            W1 + (size_t)k * HID * 6, b1 + (size_t)k * HID,
            W2 + (size_t)k * HID * HID, b2 + (size_t)k * HID,
            W3 + (size_t)k * 12 * HID,  b3 + (size_t)k * 12, k);
    }
    k_ssq_part<<<256, 256>>>();
    k_ssq_final<<<1, 256>>>();
    k_kl<<<(B + 63) / 64, 64>>>(Wsym, lvd, out);
}

// round 8
// speedup vs baseline: 1.1895x; 1.1895x over previous
#include <cuda_runtime.h>
#include <math.h>

#define B      16384
#define DIN    12
#define HID    192
#define LAYERS 24
#define NB     66
#define CAP2   120

// ---------------- scratch ----------------
__device__ float g_zk[(LAYERS + 1) * B * DIN];
__device__ float g_V [B * 72];
__device__ float g_ld[B];
__device__ float g_part[256];
__device__ float g_ssq;

// ---------------- f32x2 packed ops ----------------
union F2U { float2 f; unsigned long long u; };
__device__ __forceinline__ float2 ffma2(float2 a, float2 b, float2 c) {
    F2U A, Bv, C, D; A.f = a; Bv.f = b; C.f = c;
    asm("fma.rn.f32x2 %0,%1,%2,%3;" : "=l"(D.u) : "l"(A.u), "l"(Bv.u), "l"(C.u));
    return D.f;
}
__device__ __forceinline__ float2 fmul2(float2 a, float2 b) {
    F2U A, Bv, D; A.f = a; Bv.f = b;
    asm("mul.rn.f32x2 %0,%1,%2;" : "=l"(D.u) : "l"(A.u), "l"(Bv.u));
    return D.f;
}
__device__ __forceinline__ float2 fadd2(float2 a, float2 b) {
    F2U A, Bv, D; A.f = a; Bv.f = b;
    asm("add.rn.f32x2 %0,%1,%2;" : "=l"(D.u) : "l"(A.u), "l"(Bv.u));
    return D.f;
}

__device__ __forceinline__ float pick6(const float a[6], int i) {
    float r = a[0];
    if (i == 1) r = a[1];
    if (i == 2) r = a[2];
    if (i == 3) r = a[3];
    if (i == 4) r = a[4];
    if (i == 5) r = a[5];
    return r;
}
__device__ __forceinline__ float2 pick6f2(const float2 a[6], int i) {
    float2 r = a[0];
    if (i == 1) r = a[1];
    if (i == 2) r = a[2];
    if (i == 3) r = a[3];
    if (i == 4) r = a[4];
    if (i == 5) r = a[5];
    return r;
}

// ---------------- init ----------------
__global__ void k_init(const float* __restrict__ y, const float* __restrict__ Jp) {
    int i0 = blockIdx.x * blockDim.x + threadIdx.x;
    int st = gridDim.x * blockDim.x;
    for (int i = i0; i < B * 72; i += st) {
        g_V[i] = Jp[i];
        if (i < B * DIN) g_zk[LAYERS * B * DIN + i] = y[i];
        if (i < B)       g_ld[i] = 0.f;
    }
}

// smem float offsets
#define OFF_W2R  0        // [192][193]: W2R[a*193+b] = W2[a][b]  (a=out, b=in)
#define OFF_W3   37056    // [12][192] row-major
#define OFF_W1T  39360    // [6][192]: W1t[j*192+r] = W1[r][j]
#define OFF_B1   40512
#define OFF_B2   40704
#define OFF_B3   40896    // 16
#define OFF_WARP 40912
#define WSTRIDE  1032
// per-warp: [0,960) entries (inv list float2; vjp packets 2xfloat4, CAP2=120), [960,1032) Vw

// ---------------- fused inverse + VJP layer ----------------
__global__ void __launch_bounds__(512) k_fused(
    const float* __restrict__ W1, const float* __restrict__ b1,
    const float* __restrict__ W2, const float* __restrict__ b2,
    const float* __restrict__ W3, const float* __restrict__ b3, int k)
{
    extern __shared__ float sm[];
    int tid = threadIdx.x;

    for (int i = tid; i < HID * HID; i += 512) {
        int a = i / HID, bb = i % HID;
        sm[OFF_W2R + a * 193 + bb] = W2[i];
    }
    for (int i = tid; i < 12 * HID; i += 512) sm[OFF_W3 + i] = W3[i];
    for (int i = tid; i < HID * 6; i += 512) {
        int r = i / 6, j = i % 6;
        sm[OFF_W1T + j * 192 + r] = W1[i];
    }
    for (int i = tid; i < HID; i += 512) { sm[OFF_B1 + i] = b1[i]; sm[OFF_B2 + i] = b2[i]; }
    if (tid < 12) sm[OFF_B3 + tid] = b3[tid];
    __syncthreads();

    int lane = tid & 31, wip = tid >> 5;
    float*  wb  = sm + OFF_WARP + wip * WSTRIDE;
    float2* pw  = (float2*)wb;
    float4* pw4 = (float4*)wb;
    float*  Vw  = wb + 960;
    unsigned lt = (1u << lane) - 1u;

    const float* w2rl = sm + OFF_W2R + lane * 193;  // inverse L2 gathers (+6176*i + r)
    const float* w2rb = sm + OFF_W2R + lane;        // vjp gathers (+jj*193 + 32*i)
    const float* w3l  = sm + OFF_W3 + lane;         // +o*192 + 32*i
    const float* w1tl = sm + OFF_W1T + lane;        // +j*192 + 32*i
    const float* b1l  = sm + OFF_B1 + lane;
    const float* b2l  = sm + OFF_B2 + lane;
    const float* b3s  = sm + OFF_B3;

    int w  = (blockIdx.x * 512 + tid) >> 5;
    int nw = gridDim.x * 16;

    for (int b = w; b < B; b += nw) {
        // =========================== INVERSE PHASE ===========================
        __syncwarp();
        const float* zin = g_zk + ((size_t)(k + 1) * B + b) * DIN;
        float z1[6], z2[6];
#pragma unroll
        for (int j = 0; j < 6; j++) { z1[j] = zin[6 + j]; z2[j] = zin[j]; }

        // L1: rows r = lane + 32i (conflict-free scalar W1t reads)
        unsigned mm1[6];
        int base = 0;
#pragma unroll
        for (int i = 0; i < 6; i++) {
            float a = b1l[32 * i];
#pragma unroll
            for (int j = 0; j < 6; j++) a = fmaf(w1tl[j * 192 + 32 * i], z1[j], a);
            unsigned m = __ballot_sync(0xffffffffu, a > 0.f);
            mm1[i] = m;
            if ((m >> lane) & 1u) {
                int pos = base + __popc(m & lt);
                pw[pos] = make_float2(a, __int_as_float(lane + 32 * i));
            }
            base += __popc(m);
        }
        int cnt1 = base;
        __syncwarp();

        // L2: cols lane+32i; row-pair ffma2 packing, conflict-free gathers
        float2 hacc[6];
#pragma unroll
        for (int i = 0; i < 6; i++) hacc[i] = make_float2(b2l[32 * i], 0.f);
        {
            int c = 0;
            for (; c + 4 <= cnt1; c += 4) {
                float4 L0 = pw4[c >> 1], L1 = pw4[(c >> 1) + 1];
                const float* rp0 = w2rl + __float_as_int(L0.y);
                const float* rp1 = w2rl + __float_as_int(L0.w);
                const float* rp2 = w2rl + __float_as_int(L1.y);
                const float* rp3 = w2rl + __float_as_int(L1.w);
                float2 h01 = make_float2(L0.x, L0.z);
                float2 h23 = make_float2(L1.x, L1.z);
#pragma unroll
                for (int i = 0; i < 6; i++) {
                    hacc[i] = ffma2(make_float2(rp0[6176 * i], rp1[6176 * i]), h01, hacc[i]);
                    hacc[i] = ffma2(make_float2(rp2[6176 * i], rp3[6176 * i]), h23, hacc[i]);
                }
            }
            for (; c < cnt1; c++) {
                float2 p0 = pw[c];
                const float* rp0 = w2rl + __float_as_int(p0.y);
#pragma unroll
                for (int i = 0; i < 6; i++)
                    hacc[i].x = fmaf(rp0[6176 * i], p0.x, hacc[i].x);
            }
        }
        unsigned mm2[6];
        float h2a[6];
#pragma unroll
        for (int i = 0; i < 6; i++) {
            float hv = hacc[i].x + hacc[i].y;
            mm2[i] = __ballot_sync(0xffffffffu, hv > 0.f);
            h2a[i] = fmaxf(hv, 0.f);
        }
        float2 h2p[3];
#pragma unroll
        for (int p = 0; p < 3; p++) h2p[p] = make_float2(h2a[2 * p], h2a[2 * p + 1]);

        // L3 (i-pair packed, conflict-free scalar W3 reads)
        float pp[12];
#pragma unroll
        for (int o = 0; o < 12; o++) {
            float2 acc = make_float2(0.f, 0.f);
#pragma unroll
            for (int p = 0; p < 3; p++) {
                float2 w2 = make_float2(w3l[o * 192 + 64 * p], w3l[o * 192 + 64 * p + 32]);
                acc = ffma2(w2, h2p[p], acc);
            }
            float a = acc.x + acc.y;
#pragma unroll
            for (int off = 16; off > 0; off >>= 1) a += __shfl_xor_sync(0xffffffffu, a, off);
            pp[o] = a;
        }

        // epilogue
        float ssum = 0.f, znew[6], es[6], fac[6];
#pragma unroll
        for (int j = 0; j < 6; j++) {
            float sh = pp[2 * j] + b3s[2 * j];
            float sr = pp[2 * j + 1] + b3s[2 * j + 1];
            float s  = 2.f * tanhf(0.5f * sr);
            ssum += s;
            float em = expf(-s);
            znew[j] = (z2[j] - sh) * em;
            es[j]   = expf(s);
            float t2 = 0.5f * s;
            fac[j]  = znew[j] * es[j] * (1.f - t2 * t2);
        }
        {
            float* zo = g_zk + ((size_t)k * B + b) * DIN;
            if (lane < 12) zo[lane] = (lane < 6) ? pick6(z1, lane) : pick6(znew, lane - 6);
            if (lane == 31) g_ld[b] -= ssum;
        }

        // ============================= VJP PHASE =============================
        for (int t = lane; t < 72; t += 32) Vw[t] = g_V[(size_t)b * 72 + t];
        __syncwarp();

        // step 1 (U-factored): accv[u][i] = g-pairs @ (W3sh + fac*W3sr), cols lane+32i
        float2 accv[3][6];
#pragma unroll
        for (int u = 0; u < 3; u++)
#pragma unroll
            for (int i = 0; i < 6; i++) accv[u][i] = make_float2(0.f, 0.f);
#pragma unroll
        for (int j = 0; j < 6; j++) {
            float2 gj[3];
#pragma unroll
            for (int u = 0; u < 3; u++)
                gj[u] = make_float2(Vw[(2 * u) * 12 + j], Vw[(2 * u + 1) * 12 + j]);
            float fj = fac[j];
#pragma unroll
            for (int i = 0; i < 6; i++) {
                float wsh = w3l[(2 * j) * 192 + 32 * i];
                float wsr = w3l[(2 * j + 1) * 192 + 32 * i];
                float U = fmaf(fj, wsr, wsh);
                float2 U2 = make_float2(U, U);
#pragma unroll
                for (int u = 0; u < 3; u++) accv[u][i] = ffma2(gj[u], U2, accv[u][i]);
            }
        }

        // compact m2-active cols into 32B packets (jj*193 embedded)
        int pre = 0;
#pragma unroll
        for (int i = 0; i < 6; i++) pre += __popc(mm2[i]);
        bool hasov = (pre > CAP2);
        unsigned ovm[6];
        int base2 = 0;
#pragma unroll
        for (int i = 0; i < 6; i++) {
            unsigned m = mm2[i], keep = m;
            if (hasov) {
                int pc = __popc(m);
                int ovc = base2 + pc - CAP2;
                if (ovc > 0) {
                    if (ovc > pc) ovc = pc;
                    for (int t = 0; t < ovc; t++) keep &= ~(0x80000000u >> __clz(keep));
                }
            }
            ovm[i] = m ^ keep;
            if ((keep >> lane) & 1u) {
                int pos = base2 + __popc(keep & lt);
                int jjoff = (lane + 32 * i) * 193;
                pw4[pos * 2 + 0] = make_float4(accv[0][i].x, accv[0][i].y, accv[1][i].x, accv[1][i].y);
                pw4[pos * 2 + 1] = make_float4(accv[2][i].x, accv[2][i].y, __int_as_float(jjoff), 0.f);
            }
            base2 += __popc(keep);
        }
        int cnt2 = base2;
        __syncwarp();

        // main loop: dense output cols lane+32i, conflict-free gathers
        float2 a12[3][6];
#pragma unroll
        for (int u = 0; u < 3; u++)
#pragma unroll
            for (int i = 0; i < 6; i++) a12[u][i] = make_float2(0.f, 0.f);
#pragma unroll 2
        for (int c = 0; c < cnt2; c++) {
            float4 e0 = pw4[c * 2], e1 = pw4[c * 2 + 1];
            const float* gp = w2rb + __float_as_int(e1.z);
            float2 g01 = make_float2(e0.x, e0.y);
            float2 g23 = make_float2(e0.z, e0.w);
            float2 g45 = make_float2(e1.x, e1.y);
#pragma unroll
            for (int i = 0; i < 6; i++) {
                float wv = gp[32 * i];
                float2 wd = make_float2(wv, wv);
                a12[0][i] = ffma2(g01, wd, a12[0][i]);
                a12[1][i] = ffma2(g23, wd, a12[1][i]);
                a12[2][i] = ffma2(g45, wd, a12[2][i]);
            }
        }

        // overflow fallback (exact, ultra-rare): recompute g for dropped cols
        if (hasov) {
#pragma unroll
            for (int i = 0; i < 6; i++) {
                unsigned ov = ovm[i];
                while (ov) {
                    int src = __ffs(ov) - 1; ov &= ov - 1;
                    int jj = src + 32 * i;
                    // recompute g[v] for col jj from Vw + W3 (broadcast reads)
                    float gg[6];
#pragma unroll
                    for (int v = 0; v < 6; v++) gg[v] = 0.f;
#pragma unroll
                    for (int j = 0; j < 6; j++) {
                        float U = fmaf(fac[j], sm[OFF_W3 + (2 * j + 1) * 192 + jj],
                                       sm[OFF_W3 + (2 * j) * 192 + jj]);
#pragma unroll
                        for (int v = 0; v < 6; v++) gg[v] = fmaf(Vw[v * 12 + j], U, gg[v]);
                    }
                    float2 g01 = make_float2(gg[0], gg[1]);
                    float2 g23 = make_float2(gg[2], gg[3]);
                    float2 g45 = make_float2(gg[4], gg[5]);
                    const float* gp = w2rb + jj * 193;
#pragma unroll
                    for (int ii = 0; ii < 6; ii++) {
                        float wv = gp[32 * ii];
                        float2 wd = make_float2(wv, wv);
                        a12[0][ii] = ffma2(g01, wd, a12[0][ii]);
                        a12[1][ii] = ffma2(g23, wd, a12[1][ii]);
                        a12[2][ii] = ffma2(g45, wd, a12[2][ii]);
                    }
                }
            }
        }

        // mask (mm1) then fold through W1t (conflict-free scalar reads)
        float2 pz2[3][6];
#pragma unroll
        for (int u = 0; u < 3; u++)
#pragma unroll
            for (int j = 0; j < 6; j++) pz2[u][j] = make_float2(0.f, 0.f);
#pragma unroll
        for (int i = 0; i < 6; i++) {
            float mi = ((mm1[i] >> lane) & 1u) ? 1.f : 0.f;
            float2 md = make_float2(mi, mi);
            float2 am0 = fmul2(a12[0][i], md);
            float2 am1 = fmul2(a12[1][i], md);
            float2 am2 = fmul2(a12[2][i], md);
#pragma unroll
            for (int j = 0; j < 6; j++) {
                float wv = w1tl[j * 192 + 32 * i];
                float2 wd = make_float2(wv, wv);
                pz2[0][j] = ffma2(am0, wd, pz2[0][j]);
                pz2[1][j] = ffma2(am1, wd, pz2[1][j]);
                pz2[2][j] = ffma2(am2, wd, pz2[2][j]);
            }
        }

        // butterfly reduce (64-bit shuffles, packed adds)
#pragma unroll
        for (int u = 0; u < 3; u++)
#pragma unroll
            for (int j = 0; j < 6; j++) {
                F2U u2; u2.f = pz2[u][j];
#pragma unroll
                for (int off = 16; off > 0; off >>= 1) {
                    F2U o2; o2.u = __shfl_xor_sync(0xffffffffu, u2.u, off);
                    u2.f = fadd2(u2.f, o2.f);
                }
                pz2[u][j] = u2.f;
            }

        // parallel write: lane j < 6 writes column j
        if (lane < 6) {
            int j = lane;
            float esj = pick6(es, j);
            float* vo = g_V + (size_t)b * 72;
#pragma unroll
            for (int u = 0; u < 3; u++) {
                float2 pzv = pick6f2(pz2[u], j);
                vo[(2 * u) * 12 + j]         = Vw[(2 * u) * 12 + 6 + j] + pzv.x;
                vo[(2 * u) * 12 + 6 + j]     = Vw[(2 * u) * 12 + j] * esj;
                vo[(2 * u + 1) * 12 + j]     = Vw[(2 * u + 1) * 12 + 6 + j] + pzv.y;
                vo[(2 * u + 1) * 12 + 6 + j] = Vw[(2 * u + 1) * 12 + j] * esj;
            }
        }
    }
}

// ---------------- deterministic Frobenius-norm reduction ----------------
__global__ void k_ssq_part() {
    float s = 0.f;
    for (int i = blockIdx.x * blockDim.x + threadIdx.x; i < B * 72; i += gridDim.x * blockDim.x) {
        float v = g_V[i]; s += v * v;
    }
    __shared__ float red[256];
    red[threadIdx.x] = s; __syncthreads();
    for (int o = 128; o > 0; o >>= 1) {
        if (threadIdx.x < o) red[threadIdx.x] += red[threadIdx.x + o];
        __syncthreads();
    }
    if (threadIdx.x == 0) g_part[blockIdx.x] = red[0];
}
__global__ void k_ssq_final() {
    __shared__ float red[256];
    red[threadIdx.x] = g_part[threadIdx.x]; __syncthreads();
    for (int o = 128; o > 0; o >>= 1) {
        if (threadIdx.x < o) red[threadIdx.x] += red[threadIdx.x + o];
        __syncthreads();
    }
    if (threadIdx.x == 0) g_ssq = red[0];
}

// ---------------- KL + log_prob ----------------
#define LIX(r, c) ((r) * ((r) + 1) / 2 + (c))

__global__ void __launch_bounds__(64) k_kl(
    const float* __restrict__ Wsym, const float* __restrict__ lvd,
    float* __restrict__ out)
{
    __shared__ float As[NB * 144];
    for (int i = threadIdx.x; i < NB * 144; i += 64) {
        int m = i / 144; int rc = i % 144; int r = rc / 12; int c = rc % 12;
        As[i] = Wsym[m * 144 + r * 12 + c] - Wsym[m * 144 + c * 12 + r];
    }
    __syncthreads();

    int b = blockIdx.x * 64 + threadIdx.x;
    if (b >= B) return;

    float zr[12]; float zz = 0.f;
#pragma unroll
    for (int i = 0; i < 12; i++) { zr[i] = g_zk[(size_t)b * 12 + i]; zz += zr[i] * zr[i]; }
    out[b] = g_ld[b] - 6.f * 1.8378770664093453f - 0.5f * zz;

    float scale = rsqrtf(g_ssq);
    float Jp[6][12];
#pragma unroll
    for (int v = 0; v < 6; v++)
#pragma unroll
        for (int i = 0; i < 12; i++) Jp[v][i] = g_V[(size_t)b * 72 + v * 12 + i] * scale;

    float Sql[78];
#pragma unroll
    for (int i = 0; i < 78; i++) Sql[i] = 0.f;
    float trq = 0.f, trpq = 0.f;

    for (int m = 0; m < NB; m++) {
        const float* Am = As + m * 144;
        float Jq[12];
#pragma unroll
        for (int jj = 0; jj < 12; jj++) {
            float a = 0.f;
#pragma unroll
            for (int i = 0; i < 12; i++) a = fmaf(zr[i], Am[jj * 12 + i], a);
            Jq[jj] = a; trq = fmaf(a, a, trq);
        }
#pragma unroll
        for (int n = 0; n < 12; n++)
#pragma unroll
            for (int mm = 0; mm <= n; mm++) Sql[LIX(n, mm)] = fmaf(Jq[n], Jq[mm], Sql[LIX(n, mm)]);
#pragma unroll
        for (int v = 0; v < 6; v++) {
            float d = 0.f;
#pragma unroll
            for (int i = 0; i < 12; i++) d = fmaf(Jp[v][i], Jq[i], d);
            trpq = fmaf(d, d, trpq);
        }
    }

    float Ml[21];
#pragma unroll
    for (int a = 0; a < 6; a++)
#pragma unroll
        for (int c = 0; c <= a; c++) {
            float acc = 0.f;
#pragma unroll
            for (int i = 0; i < 12; i++) acc = fmaf(Jp[a][i], Jp[c][i], acc);
            Ml[LIX(a, c)] = acc;
        }
#pragma unroll
    for (int d = 0; d < 6; d++) Ml[LIX(d, d)] += 1e-3f;
    float dm = 0.f;
#pragma unroll
    for (int d = 0; d < 6; d++) dm += Ml[LIX(d, d)];
    float normM = fmaxf(dm * (1.f / 6.f), 1e-6f);
#pragma unroll
    for (int d = 0; d < 6; d++) Ml[LIX(d, d)] += 1e-3f * normM;

    float D[12];
#pragma unroll
    for (int i = 0; i < 12; i++) D[i] = expf(-lvd[i]);
#pragma unroll
    for (int d = 0; d < 12; d++) Sql[LIX(d, d)] += D[d];
    float dh = 0.f;
#pragma unroll
    for (int d = 0; d < 12; d++) dh += Sql[LIX(d, d)];
    float normH = fmaxf(dh * (1.f / 12.f), 1e-6f);
#pragma unroll
    for (int d = 0; d < 12; d++) Sql[LIX(d, d)] += 1e-3f * normH;

    float Db[12], sumDb = 0.f;
#pragma unroll
    for (int i = 0; i < 12; i++) { Db[i] = D[i] + 1e-3f * normH; sumDb += Db[i]; }

    float trp = 0.f;
#pragma unroll
    for (int v = 0; v < 6; v++)
#pragma unroll
        for (int i = 0; i < 12; i++) trp = fmaf(Jp[v][i] * Jp[v][i], Db[i], trp);

    float trace = (1e-3f + 1e-3f * normM) * (sumDb + trq) + trp + trpq;

    float ldM = 0.f;
#pragma unroll
    for (int c = 0; c < 6; c++) {
        float d = Ml[LIX(c, c)];
#pragma unroll
        for (int kk = 0; kk < c; kk++) d -= Ml[LIX(c, kk)] * Ml[LIX(c, kk)];
        d = sqrtf(d); ldM += 2.f * logf(d);
        float inv = 1.f / d;
#pragma unroll
        for (int r = c + 1; r < 6; r++) {
            float a = Ml[LIX(r, c)];
#pragma unroll
            for (int kk = 0; kk < c; kk++) a -= Ml[LIX(r, kk)] * Ml[LIX(c, kk)];
            Ml[LIX(r, c)] = a * inv;
        }
    }
    float ldH = 0.f;
#pragma unroll
    for (int c = 0; c < 12; c++) {
        float d = Sql[LIX(c, c)];
#pragma unroll
        for (int kk = 0; kk < c; kk++) d -= Sql[LIX(c, kk)] * Sql[LIX(c, kk)];
        d = sqrtf(d); ldH += 2.f * logf(d);
        float inv = 1.f / d;
#pragma unroll
        for (int r = c + 1; r < 12; r++) {
            float a = Sql[LIX(r, c)];
#pragma unroll
            for (int kk = 0; kk < c; kk++) a -= Sql[LIX(r, kk)] * Sql[LIX(c, kk)];
            Sql[LIX(r, c)] = a * inv;
        }
    }

    float logdet_p = ldM + 6.f * (-6.907755278982137f);
    out[B + b] = 0.5f * (trace - logdet_p - ldH - 12.f);
}

// ---------------- host launcher ----------------
extern "C" void kernel_launch(void* const* d_in, const int* in_sizes, int n_in,
                              void* d_out, int out_size) {
    const float* y    = (const float*)d_in[0];
    const float* Jp   = (const float*)d_in[1];
    const float* W1   = (const float*)d_in[2];
    const float* b1   = (const float*)d_in[3];
    const float* W2   = (const float*)d_in[4];
    const float* b2   = (const float*)d_in[5];
    const float* W3   = (const float*)d_in[6];
    const float* b3   = (const float*)d_in[7];
    const float* Wsym = (const float*)d_in[8];
    const float* lvd  = (const float*)d_in[9];
    float* out = (float*)d_out;

    const int SMEM_F = (OFF_WARP + 16 * WSTRIDE) * 4;  // 229,696 B
    cudaFuncSetAttribute(k_fused, cudaFuncAttributeMaxDynamicSharedMemorySize, SMEM_F);

    k_init<<<256, 256>>>(y, Jp);

    for (int k = LAYERS - 1; k >= 0; k--) {
        k_fused<<<152, 512, SMEM_F>>>(
            W1 + (size_t)k * HID * 6, b1 + (size_t)k * HID,
            W2 + (size_t)k * HID * HID, b2 + (size_t)k * HID,
            W3 + (size_t)k * 12 * HID,  b3 + (size_t)k * 12, k);
    }
    k_ssq_part<<<256, 256>>>();
    k_ssq_final<<<1, 256>>>();
    k_kl<<<(B + 63) / 64, 64>>>(Wsym, lvd, out);
}